// round 13
// baseline (speedup 1.0000x reference)
#include <cuda_runtime.h>

// Problem constants
#define B_ 8
#define C_ 256
#define N_ 16384
#define K_ 128

// Decomposition: CTA = (batch, 64-channel slice, 1-of-19 N interleave)
#define SLICE_C 64
#define NSLICE 4                // C_/SLICE_C
#define NS 19                   // N interleave -> 8*4*19 = 608 CTAs = 4/SM exactly
#define TN 64                   // points per chunk
#define TPB 256
#define NCHUNKS (N_ / TN)       // 256 chunks, round-robin over NS
#define TROW 68                 // padded row stride (floats/uints)
#define TAB_U (K_ * TROW)       // 8704 uints per-CTA table

// Per-CTA partial tables: 608 x 34.8KB ~= 21 MB.
__device__ unsigned int g_scratch[B_ * NSLICE * NS * TAB_U];

// Monotone float -> uint key: unsigned order == float order.
__device__ __forceinline__ unsigned int fkey(float f) {
    int i = __float_as_int(f);
    return (i >= 0) ? ((unsigned int)i | 0x80000000u) : ~(unsigned int)i;
}
__device__ __forceinline__ float funkey(unsigned int k) {
    unsigned int i = (k & 0x80000000u) ? (k & 0x7FFFFFFFu) : ~k;
    return __int_as_float((int)i);
}

// Branch-free conditional shared max: SETP + @p RED.SHARED.
__device__ __forceinline__ void smax_if(unsigned int* cell, unsigned int cur,
                                        unsigned int key) {
    unsigned int addr = (unsigned int)__cvta_generic_to_shared(cell);
    asm volatile(
        "{\n\t.reg .pred p;\n\t"
        "setp.lt.u32 p, %1, %2;\n\t"
        "@p red.shared.max.u32 [%0], %2;\n\t}"
        :: "r"(addr), "r"(cur), "r"(key) : "memory");
}

// Phase 1: fused transpose + per-CTA segment-max, 2-deep reg pipeline, 4 CTAs/SM.
__global__ __launch_bounds__(TPB, 4)
void seg_phase1(const float* __restrict__ pf, const int* __restrict__ cids,
                float* __restrict__ out_pf) {
    extern __shared__ unsigned int smem[];
    unsigned int* tab = smem;                          // [K][TROW], 34.8 KB
    float* tile = (float*)(smem + TAB_U);              // [TN][TROW] point-major
    int* scid = (int*)(tile + TN * TROW);              // TN ids

    const int tid = threadIdx.x;
    const int b = blockIdx.y;
    const int cslice = blockIdx.x / NS;                // 0..3
    const int ns = blockIdx.x - cslice * NS;           // 0..18

    {   // init table
        uint4 z = make_uint4(0u, 0u, 0u, 0u);
        uint4* t4 = (uint4*)tab;
        #pragma unroll
        for (int i = tid; i < TAB_U / 4; i += TPB) t4[i] = z;
    }

    const float* src = pf + (size_t)b * C_ * N_ + (size_t)cslice * SLICE_C * N_;
    const int* cidp = cids + b * N_;

    // chunk count: 256 = 19*13 + 9 -> ns<9 get 14, else 13
    const int cnt = (NCHUNKS / NS) + (ns < (NCHUNKS % NS) ? 1 : 0);

    // Loader: thread owns point ln, 4 channel quads cg4 + {0,16,32,48}
    const int ln = tid & 63;
    const int cg4 = (tid >> 6) * 4;     // 0,4,8,12
    // Consumer: 4 consecutive channels per thread; 16 points per pass, 4 passes
    const int c4 = (tid & 15) * 4;      // 0..60
    const int pb = tid >> 4;            // 0..15

    auto prefetch = [&](int i, float* rr, int& cidr) {
        const int m = ns + NS * i;
        const float* p0 = src + (size_t)cg4 * N_ + m * TN + ln;
        #pragma unroll
        for (int h = 0; h < 4; h++) {
            #pragma unroll
            for (int j = 0; j < 4; j++)
                rr[4 * h + j] = __ldcs(p0 + (size_t)(16 * h + j) * N_);
        }
        if (tid < TN) cidr = cidp[m * TN + tid];
    };

    float rA[16], rB[16];
    int cidA = 0, cidB = 0;
    prefetch(0, rA, cidA);
    if (cnt > 1) prefetch(1, rB, cidB);

    auto body = [&](int i, float* rr, int& cidr) {
        __syncthreads();                               // prev tile fully consumed
        #pragma unroll
        for (int h = 0; h < 4; h++)
            *(float4*)(tile + ln * TROW + cg4 + 16 * h) =
                make_float4(rr[4 * h], rr[4 * h + 1], rr[4 * h + 2], rr[4 * h + 3]);
        if (tid < TN) scid[tid] = cidr;
        __syncthreads();                               // tile + scid ready

        if (i + 2 < cnt) prefetch(i + 2, rr, cidr);    // refill freed buffer

        const int n0 = (ns + NS * i) * TN;
        #pragma unroll
        for (int q = 0; q < 4; q++) {
            const int p = pb + q * 16;
            float4 vv = *(const float4*)(tile + p * TROW + c4);
            __stcs((float4*)(out_pf + ((size_t)b * N_ + n0 + p) * C_
                             + cslice * SLICE_C + c4), vv);
            const int cid = scid[p];
            const int en = (cid >= 0);
            unsigned int* cell = &tab[(en ? cid : 0) * TROW + c4];
            uint4 cur = *(const uint4*)cell;           // LDS.128 filter read
            unsigned int k0 = en ? fkey(vv.x) : 0u;
            unsigned int k1 = en ? fkey(vv.y) : 0u;
            unsigned int k2 = en ? fkey(vv.z) : 0u;
            unsigned int k3 = en ? fkey(vv.w) : 0u;
            smax_if(cell + 0, cur.x, k0);
            smax_if(cell + 1, cur.y, k1);
            smax_if(cell + 2, cur.z, k2);
            smax_if(cell + 3, cur.w, k3);
        }
    };

    int i = 0;
    #pragma unroll 1
    for (; i + 1 < cnt; i += 2) {
        body(i,     rA, cidA);
        body(i + 1, rB, cidB);
    }
    if (i < cnt) body(i, rA, cidA);                    // odd tail
    __syncthreads();

    // dump table (plain stores)
    uint4* dst = (uint4*)(g_scratch
                 + (size_t)((b * NSLICE + cslice) * NS + ns) * TAB_U);
    const uint4* t4 = (const uint4*)tab;
    #pragma unroll
    for (int i2 = tid; i2 < TAB_U / 4; i2 += TPB) dst[i2] = t4[i2];
}

// Phase 2: one thread per output scalar; NS independent 4B loads (MLP=19).
__global__ __launch_bounds__(256)
void seg_phase2(float* __restrict__ out_seg) {
    int g = blockIdx.x * blockDim.x + threadIdx.x;     // 0 .. B*K*C-1
    int c = g & (C_ - 1);
    int k = (g >> 8) & (K_ - 1);
    int b = g >> 15;
    int slice = c >> 6;
    int cc = c & (SLICE_C - 1);
    const unsigned int* base = g_scratch
        + (size_t)((b * NSLICE + slice) * NS) * TAB_U + k * TROW + cc;
    unsigned int mx = 0u;
    #pragma unroll
    for (int s = 0; s < NS; s++)
        mx = max(mx, base[(size_t)s * TAB_U]);
    out_seg[g] = mx ? funkey(mx) : 0.0f;
}

extern "C" void kernel_launch(void* const* d_in, const int* in_sizes, int n_in,
                              void* d_out, int out_size) {
    const float* pf = (const float*)d_in[0];      // (B,C,N) f32
    const int* cid  = (const int*)d_in[1];        // (B,N) i32
    float* out      = (float*)d_out;
    float* out_seg  = out;                        // (B*K, C)
    float* out_pf   = out + (size_t)B_ * K_ * C_; // (B*N, C)

    const size_t smem_bytes = (size_t)TAB_U * 4 + (size_t)TN * TROW * 4 + (size_t)TN * 4;
    cudaFuncSetAttribute(seg_phase1, cudaFuncAttributeMaxDynamicSharedMemorySize,
                         (int)smem_bytes);

    dim3 grid(NSLICE * NS, B_);                   // 76 x 8 = 608 CTAs, 4/SM
    seg_phase1<<<grid, TPB, smem_bytes>>>(pf, cid, out_pf);

    seg_phase2<<<(B_ * K_ * C_) / 256, 256>>>(out_seg);
}

// round 14
// speedup vs baseline: 1.2341x; 1.2341x over previous
#include <cuda_runtime.h>

// Problem constants
#define B_ 8
#define C_ 256
#define N_ 16384
#define K_ 128

// Decomposition: CTA = (batch, 64-channel slice, 1-of-9 N interleave)
#define SLICE_C 64
#define NSLICE 4                // C_/SLICE_C
#define NS 9                    // N interleave -> 8*4*9 = 288 CTAs, 2/SM
#define TN 128                  // points per chunk (doubled: halves barrier count)
#define TPB 512
#define NCHUNKS (N_ / TN)       // 128 chunks, round-robin over NS
#define TROW 68                 // padded row stride (floats/uints)
#define TAB_U (K_ * TROW)       // 8704 uints per-CTA table

// Per-CTA partial tables: 288 x 34.8KB ~= 10 MB.
__device__ unsigned int g_scratch[B_ * NSLICE * NS * TAB_U];

// Monotone float -> uint key: unsigned order == float order.
__device__ __forceinline__ unsigned int fkey(float f) {
    int i = __float_as_int(f);
    return (i >= 0) ? ((unsigned int)i | 0x80000000u) : ~(unsigned int)i;
}
__device__ __forceinline__ float funkey(unsigned int k) {
    unsigned int i = (k & 0x80000000u) ? (k & 0x7FFFFFFFu) : ~k;
    return __int_as_float((int)i);
}

// Branch-free conditional shared max: SETP + @p RED.SHARED.
__device__ __forceinline__ void smax_if(unsigned int* cell, unsigned int cur,
                                        unsigned int key) {
    unsigned int addr = (unsigned int)__cvta_generic_to_shared(cell);
    asm volatile(
        "{\n\t.reg .pred p;\n\t"
        "setp.lt.u32 p, %1, %2;\n\t"
        "@p red.shared.max.u32 [%0], %2;\n\t}"
        :: "r"(addr), "r"(cur), "r"(key) : "memory");
}

// Phase 1: fused transpose + per-CTA segment-max, 2-deep reg pipeline, 2 CTAs/SM.
__global__ __launch_bounds__(TPB, 2)
void seg_phase1(const float* __restrict__ pf, const int* __restrict__ cids,
                float* __restrict__ out_pf) {
    extern __shared__ unsigned int smem[];
    unsigned int* tab = smem;                          // [K][TROW], 34.8 KB
    float* tile = (float*)(smem + TAB_U);              // [TN][TROW] point-major, 34.8 KB
    int* scid = (int*)(tile + TN * TROW);              // TN ids

    const int tid = threadIdx.x;
    const int b = blockIdx.y;
    const int cslice = blockIdx.x / NS;                // 0..3
    const int ns = blockIdx.x - cslice * NS;           // 0..8

    {   // init table
        uint4 z = make_uint4(0u, 0u, 0u, 0u);
        uint4* t4 = (uint4*)tab;
        #pragma unroll
        for (int i = tid; i < TAB_U / 4; i += TPB) t4[i] = z;
    }

    const float* src = pf + (size_t)b * C_ * N_ + (size_t)cslice * SLICE_C * N_;
    const int* cidp = cids + b * N_;

    // chunk count: 128 = 9*14 + 2 -> ns<2 get 15, else 14
    const int cnt = (NCHUNKS / NS) + (ns < (NCHUNKS % NS) ? 1 : 0);

    // Loader: thread owns point ln, 4 channel quads cg4 + 16h (h=0..3)
    const int ln = tid & 127;
    const int cg4 = (tid >> 7) * 4;     // 0,4,8,12
    // Consumer: 4 consecutive channels per thread; 32 points per pass, 4 passes
    const int c4 = (tid & 15) * 4;      // 0..60
    const int pb = tid >> 4;            // 0..31

    auto prefetch = [&](int i, float* rr, int& cidr) {
        const int m = ns + NS * i;
        const float* p0 = src + (size_t)cg4 * N_ + m * TN + ln;
        #pragma unroll
        for (int h = 0; h < 4; h++) {
            #pragma unroll
            for (int j = 0; j < 4; j++)
                rr[4 * h + j] = __ldcs(p0 + (size_t)(16 * h + j) * N_);
        }
        if (tid < TN) cidr = cidp[m * TN + tid];
    };

    float rA[16], rB[16];
    int cidA = 0, cidB = 0;
    prefetch(0, rA, cidA);
    if (cnt > 1) prefetch(1, rB, cidB);

    auto body = [&](int i, float* rr, int& cidr) {
        __syncthreads();                               // prev tile fully consumed
        #pragma unroll
        for (int h = 0; h < 4; h++)
            *(float4*)(tile + ln * TROW + cg4 + 16 * h) =
                make_float4(rr[4 * h], rr[4 * h + 1], rr[4 * h + 2], rr[4 * h + 3]);
        if (tid < TN) scid[tid] = cidr;
        __syncthreads();                               // tile + scid ready

        if (i + 2 < cnt) prefetch(i + 2, rr, cidr);    // refill freed buffer

        const int n0 = (ns + NS * i) * TN;
        #pragma unroll
        for (int q = 0; q < 4; q++) {
            const int p = pb + q * 32;
            float4 vv = *(const float4*)(tile + p * TROW + c4);
            __stcs((float4*)(out_pf + ((size_t)b * N_ + n0 + p) * C_
                             + cslice * SLICE_C + c4), vv);
            const int cid = scid[p];
            const int en = (cid >= 0);
            unsigned int* cell = &tab[(en ? cid : 0) * TROW + c4];
            uint4 cur = *(const uint4*)cell;           // LDS.128 filter read
            unsigned int k0 = en ? fkey(vv.x) : 0u;
            unsigned int k1 = en ? fkey(vv.y) : 0u;
            unsigned int k2 = en ? fkey(vv.z) : 0u;
            unsigned int k3 = en ? fkey(vv.w) : 0u;
            smax_if(cell + 0, cur.x, k0);
            smax_if(cell + 1, cur.y, k1);
            smax_if(cell + 2, cur.z, k2);
            smax_if(cell + 3, cur.w, k3);
        }
    };

    int i = 0;
    #pragma unroll 1
    for (; i + 1 < cnt; i += 2) {
        body(i,     rA, cidA);
        body(i + 1, rB, cidB);
    }
    if (i < cnt) body(i, rA, cidA);                    // odd tail
    __syncthreads();

    // dump table (plain stores)
    uint4* dst = (uint4*)(g_scratch
                 + (size_t)((b * NSLICE + cslice) * NS + ns) * TAB_U);
    const uint4* t4 = (const uint4*)tab;
    #pragma unroll
    for (int i2 = tid; i2 < TAB_U / 4; i2 += TPB) dst[i2] = t4[i2];
}

// Phase 2: one thread per output scalar; NS independent 4B loads (MLP=9).
__global__ __launch_bounds__(256)
void seg_phase2(float* __restrict__ out_seg) {
    int g = blockIdx.x * blockDim.x + threadIdx.x;     // 0 .. B*K*C-1
    int c = g & (C_ - 1);
    int k = (g >> 8) & (K_ - 1);
    int b = g >> 15;
    int slice = c >> 6;
    int cc = c & (SLICE_C - 1);
    const unsigned int* base = g_scratch
        + (size_t)((b * NSLICE + slice) * NS) * TAB_U + k * TROW + cc;
    unsigned int mx = 0u;
    #pragma unroll
    for (int s = 0; s < NS; s++)
        mx = max(mx, base[(size_t)s * TAB_U]);
    out_seg[g] = mx ? funkey(mx) : 0.0f;
}

extern "C" void kernel_launch(void* const* d_in, const int* in_sizes, int n_in,
                              void* d_out, int out_size) {
    const float* pf = (const float*)d_in[0];      // (B,C,N) f32
    const int* cid  = (const int*)d_in[1];        // (B,N) i32
    float* out      = (float*)d_out;
    float* out_seg  = out;                        // (B*K, C)
    float* out_pf   = out + (size_t)B_ * K_ * C_; // (B*N, C)

    const size_t smem_bytes = (size_t)TAB_U * 4 + (size_t)TN * TROW * 4 + (size_t)TN * 4;
    cudaFuncSetAttribute(seg_phase1, cudaFuncAttributeMaxDynamicSharedMemorySize,
                         (int)smem_bytes);

    dim3 grid(NSLICE * NS, B_);                   // 36 x 8 = 288 CTAs, 2/SM
    seg_phase1<<<grid, TPB, smem_bytes>>>(pf, cid, out_pf);

    seg_phase2<<<(B_ * K_ * C_) / 256, 256>>>(out_seg);
}